// round 5
// baseline (speedup 1.0000x reference)
#include <cuda_runtime.h>

#define N_NODES 100000
#define N_EDGES 1600000
#define F_INP   8
#define H       128
#define NLAYERS 4
#define E_FEAT  16
#define NG      256
#define OUT_F   256

#define SCAN_CHUNK 512
#define SCAN_NBLK  196   // 196*512 = 100352 >= N_NODES

typedef unsigned long long u64;

// ---------------- scratch (device globals; allocations forbidden) ----------------
__device__ __align__(16) float g_h   [(size_t)N_NODES * H];
__device__ __align__(16) float g_agg [(size_t)N_NODES * H];
__device__ __align__(16) float g_hc  [(size_t)N_NODES * H];
__device__ __align__(16) float g_stats[2 * H];
__device__ __align__(16) float g_bn   [2 * H];
__device__ __align__(16) float g_hp  [NG * H];
__device__ float g_cntg[NG];

__device__ int g_cnt_i [N_NODES];      // degree; self-cleaned each call
__device__ int g_done  [N_NODES];      // bucket completion; self-cleaned
__device__ int g_rowptr[N_NODES + 1];
__device__ int g_cursor[N_NODES];
__device__ int g_eix   [N_EDGES];
__device__ int g_srcx  [N_EDGES];
// attr in CSR order, each value duplicated as (a,a) for direct f32x2 FMA
__device__ __align__(16) u64 g_attrs2[(size_t)N_EDGES * E_FEAT];

// ---------------- f32x2 helpers ----------------
__device__ __forceinline__ u64 pk2(float x, float y) {
    u64 r; asm("mov.b64 %0,{%1,%2};" : "=l"(r) : "f"(x), "f"(y)); return r;
}
__device__ __forceinline__ void up2(u64 p, float& x, float& y) {
    asm("mov.b64 {%0,%1},%2;" : "=f"(x), "=f"(y) : "l"(p));
}
__device__ __forceinline__ u64 fma2(u64 a, u64 b, u64 c) {
    u64 d; asm("fma.rn.f32x2 %0,%1,%2,%3;" : "=l"(d) : "l"(a), "l"(b), "l"(c)); return d;
}

// ================= my launch 0: embed + degree histogram + zero =================
#define MEGA_EMBED_BLKS  N_NODES
#define MEGA_HIST_BLKS   ((N_EDGES + 127) / 128)
#define MEGA_ZERO_BLKS   ((NG * H + 127) / 128)
__global__ void k_megainit(const float* __restrict__ x,
                           const float* __restrict__ W,
                           const float* __restrict__ b,
                           const int* __restrict__ ei) {
    int blk = blockIdx.x;
    int t = threadIdx.x;
    if (blk < MEGA_EMBED_BLKS) {
        const float* xr = x + (size_t)blk * F_INP;
        float acc = b[t];
#pragma unroll
        for (int k = 0; k < F_INP; k++)
            acc = fmaf(xr[k], W[k * H + t], acc);
        g_h[(size_t)blk * H + t] = acc;
        return;
    }
    blk -= MEGA_EMBED_BLKS;
    if (blk < MEGA_HIST_BLKS) {
        int e = blk * 128 + t;
        if (e < N_EDGES) atomicAdd(&g_cnt_i[ei[N_EDGES + e]], 1);
        return;
    }
    blk -= MEGA_HIST_BLKS;
    int i = blk * 128 + t;
    if (i < NG * H) g_hp[i] = 0.f;
    if (i < NG)     g_cntg[i] = 0.f;
}

// ================= my launch 1: fused exclusive scan -> rowptr, cursor =================
// Each block recomputes its cross-chunk base by summing all counts before its chunk.
__global__ void __launch_bounds__(SCAN_CHUNK) k_scanfused() {
    __shared__ int s[SCAN_CHUNK];
    __shared__ int sb[SCAN_CHUNK];
    int t = threadIdx.x;
    int lim = blockIdx.x * SCAN_CHUNK;   // sum counts [0, lim)

    int acc = 0;
    const int4* c4 = (const int4*)g_cnt_i;
    for (int i4 = t; i4 < lim / 4; i4 += SCAN_CHUNK) {
        int4 v = c4[i4];
        acc += v.x + v.y + v.z + v.w;
    }
    sb[t] = acc; __syncthreads();
    for (int o = SCAN_CHUNK / 2; o > 0; o >>= 1) {
        if (t < o) sb[t] += sb[t + o];
        __syncthreads();
    }
    int base = sb[0];

    int i = lim + t;
    int v = (i < N_NODES) ? g_cnt_i[i] : 0;
    s[t] = v; __syncthreads();
    for (int o = 1; o < SCAN_CHUNK; o <<= 1) {
        int tv = (t >= o) ? s[t - o] : 0;
        __syncthreads();
        s[t] += tv;
        __syncthreads();
    }
    if (i < N_NODES) {
        int ex = base + s[t] - v;
        g_rowptr[i] = ex;
        g_cursor[i] = ex;
        if (i == N_NODES - 1) g_rowptr[N_NODES] = base + s[t];
    }
}

// ================= my launch 2: fill + per-bucket sort + build (fused) =================
// Last edge-thread to arrive at a bucket sorts it (determinism) and emits srcx/attrs2.
__global__ void k_fillsort(const int* __restrict__ ei, const float* __restrict__ attr) {
    int e = blockIdx.x * blockDim.x + threadIdx.x;
    if (e >= N_EDGES) return;
    int d = ei[N_EDGES + e];
    int pos = atomicAdd(&g_cursor[d], 1);
    g_eix[pos] = e;
    __threadfence();
    int cnt = g_cnt_i[d];
    if (atomicAdd(&g_done[d], 1) == cnt - 1) {
        __threadfence();
        int row = g_rowptr[d], end = row + cnt;
        for (int i = row + 1; i < end; i++) {
            int key = g_eix[i];
            int j = i - 1;
            while (j >= row && g_eix[j] > key) { g_eix[j + 1] = g_eix[j]; j--; }
            g_eix[j + 1] = key;
        }
        for (int p = row; p < end; p++) {
            int ee = g_eix[p];
            g_srcx[p] = ei[ee];
            const float4* ar = (const float4*)(attr + (size_t)ee * E_FEAT);
            u64* aw = g_attrs2 + (size_t)p * E_FEAT;
#pragma unroll
            for (int q = 0; q < 4; q++) {
                float4 a = ar[q];
                aw[q * 4 + 0] = pk2(a.x, a.x);
                aw[q * 4 + 1] = pk2(a.y, a.y);
                aw[q * 4 + 2] = pk2(a.z, a.z);
                aw[q * 4 + 3] = pk2(a.w, a.w);
            }
        }
        g_cnt_i[d] = 0;   // self-clean for next graph replay
        g_done[d]  = 0;
    }
}

// ================= my launch 3 (+ per layer): gather + aggregate =================
// agg[d] = h[d] + sum_{e in CSR(d)} relu(h[src_e] + attr_e @ W + b)
// One warp per dst; 2 edges in flight; no SHFL — attrs read as pre-packed (a,a)
// u64 broadcasts feeding fma.rn.f32x2 directly.
__global__ void __launch_bounds__(256) k_gatheragg(const float* __restrict__ W,
                                                   const float* __restrict__ b) {
    int lane = threadIdx.x & 31;
    int d = blockIdx.x * 8 + (threadIdx.x >> 5);
    if (d >= N_NODES) return;

    u64 w01[E_FEAT], w23[E_FEAT];
#pragma unroll
    for (int k = 0; k < E_FEAT; k++) {
        ulonglong2 wp = *(const ulonglong2*)(W + k * H + lane * 4);
        w01[k] = wp.x; w23[k] = wp.y;
    }
    float4 bb = *(const float4*)(b + lane * 4);
    u64 b01 = pk2(bb.x, bb.y), b23 = pk2(bb.z, bb.w);

    int row = g_rowptr[d], end = g_rowptr[d + 1];
    float4 acc = *(const float4*)(g_h + (size_t)d * H + lane * 4);

    int j = row;
    for (; j + 2 <= end; j += 2) {
        int s0 = g_srcx[j], s1 = g_srcx[j + 1];
        float4 h0 = *(const float4*)(g_h + (size_t)s0 * H + lane * 4);
        float4 h1 = *(const float4*)(g_h + (size_t)s1 * H + lane * 4);
        const ulonglong2* ar0 = (const ulonglong2*)(g_attrs2 + (size_t)j * E_FEAT);
        const ulonglong2* ar1 = (const ulonglong2*)(g_attrs2 + (size_t)(j + 1) * E_FEAT);
        u64 p01 = b01, p23 = b23, q01 = b01, q23 = b23;
#pragma unroll
        for (int k2 = 0; k2 < E_FEAT / 2; k2++) {
            ulonglong2 aa = ar0[k2];
            ulonglong2 cc = ar1[k2];
            p01 = fma2(aa.x, w01[2 * k2],     p01);
            p23 = fma2(aa.x, w23[2 * k2],     p23);
            p01 = fma2(aa.y, w01[2 * k2 + 1], p01);
            p23 = fma2(aa.y, w23[2 * k2 + 1], p23);
            q01 = fma2(cc.x, w01[2 * k2],     q01);
            q23 = fma2(cc.x, w23[2 * k2],     q23);
            q01 = fma2(cc.y, w01[2 * k2 + 1], q01);
            q23 = fma2(cc.y, w23[2 * k2 + 1], q23);
        }
        float e0, e1, e2, e3, f0, f1, f2, f3;
        up2(p01, e0, e1); up2(p23, e2, e3);
        up2(q01, f0, f1); up2(q23, f2, f3);
        acc.x += fmaxf(h0.x + e0, 0.f) + fmaxf(h1.x + f0, 0.f);
        acc.y += fmaxf(h0.y + e1, 0.f) + fmaxf(h1.y + f1, 0.f);
        acc.z += fmaxf(h0.z + e2, 0.f) + fmaxf(h1.z + f2, 0.f);
        acc.w += fmaxf(h0.w + e3, 0.f) + fmaxf(h1.w + f3, 0.f);
    }
    if (j < end) {
        int s0 = g_srcx[j];
        float4 h0 = *(const float4*)(g_h + (size_t)s0 * H + lane * 4);
        const ulonglong2* ar0 = (const ulonglong2*)(g_attrs2 + (size_t)j * E_FEAT);
        u64 p01 = b01, p23 = b23;
#pragma unroll
        for (int k2 = 0; k2 < E_FEAT / 2; k2++) {
            ulonglong2 aa = ar0[k2];
            p01 = fma2(aa.x, w01[2 * k2],     p01);
            p23 = fma2(aa.x, w23[2 * k2],     p23);
            p01 = fma2(aa.y, w01[2 * k2 + 1], p01);
            p23 = fma2(aa.y, w23[2 * k2 + 1], p23);
        }
        float e0, e1, e2, e3;
        up2(p01, e0, e1); up2(p23, e2, e3);
        acc.x += fmaxf(h0.x + e0, 0.f);
        acc.y += fmaxf(h0.y + e1, 0.f);
        acc.z += fmaxf(h0.z + e2, 0.f);
        acc.w += fmaxf(h0.w + e3, 0.f);
    }
    *(float4*)(g_agg + (size_t)d * H + lane * 4) = acc;
}

// ================= node GEMM: hc = agg @ nn_W + nn_b ; BN sum/sumsq =================
__global__ void __launch_bounds__(256) k_nodegemm(const float* __restrict__ W,
                                                  const float* __restrict__ b) {
    extern __shared__ float sW[];   // 64KB
    for (int idx = threadIdx.x; idx < H * H / 4; idx += blockDim.x)
        ((float4*)sW)[idx] = ((const float4*)W)[idx];
    __syncthreads();

    int lane = threadIdx.x & 31;
    int wid  = (blockIdx.x * blockDim.x + threadIdx.x) >> 5;
    int nw   = (gridDim.x * blockDim.x) >> 5;
    float4 bb = *(const float4*)(b + lane * 4);
    u64 bias01 = pk2(bb.x, bb.y), bias23 = pk2(bb.z, bb.w);

    float4 sum = make_float4(0, 0, 0, 0);
    float4 sq  = make_float4(0, 0, 0, 0);

    for (int i0 = wid * 8; i0 < N_NODES; i0 += nw * 8) {
        u64 acc01[8], acc23[8];
#pragma unroll
        for (int n = 0; n < 8; n++) { acc01[n] = bias01; acc23[n] = bias23; }

#pragma unroll 4
        for (int k4 = 0; k4 < H; k4 += 4) {
            float4 av[8];
#pragma unroll
            for (int n = 0; n < 8; n++)
                av[n] = *(const float4*)(g_agg + (size_t)(i0 + n) * H + k4);
#pragma unroll
            for (int kk = 0; kk < 4; kk++) {
                ulonglong2 wp = *(const ulonglong2*)(sW + (k4 + kk) * H + lane * 4);
#pragma unroll
                for (int n = 0; n < 8; n++) {
                    float a = (kk == 0) ? av[n].x : (kk == 1) ? av[n].y
                             : (kk == 2) ? av[n].z : av[n].w;
                    u64 ap = pk2(a, a);
                    acc01[n] = fma2(ap, wp.x, acc01[n]);
                    acc23[n] = fma2(ap, wp.y, acc23[n]);
                }
            }
        }
#pragma unroll
        for (int n = 0; n < 8; n++) {
            float x0, x1, x2, x3;
            up2(acc01[n], x0, x1); up2(acc23[n], x2, x3);
            *(float4*)(g_hc + (size_t)(i0 + n) * H + lane * 4) =
                make_float4(x0, x1, x2, x3);
            sum.x += x0; sum.y += x1; sum.z += x2; sum.w += x3;
            sq.x += x0 * x0; sq.y += x1 * x1; sq.z += x2 * x2; sq.w += x3 * x3;
        }
    }
    int f = lane * 4;
    atomicAdd(&g_stats[f + 0], sum.x);
    atomicAdd(&g_stats[f + 1], sum.y);
    atomicAdd(&g_stats[f + 2], sum.z);
    atomicAdd(&g_stats[f + 3], sum.w);
    atomicAdd(&g_stats[H + f + 0], sq.x);
    atomicAdd(&g_stats[H + f + 1], sq.y);
    atomicAdd(&g_stats[H + f + 2], sq.z);
    atomicAdd(&g_stats[H + f + 3], sq.w);
}

__global__ void k_bnstats() {
    int j = threadIdx.x;
    float s = g_stats[j];
    float q = g_stats[H + j];
    const float inv = 1.0f / (float)N_NODES;
    float mu  = s * inv;
    float var = q * inv - mu * mu;
    g_bn[j]     = mu;
    g_bn[H + j] = rsqrtf(var + 1e-5f);
    g_stats[j] = 0.f;
    g_stats[H + j] = 0.f;
}

__global__ void k_apply(const float* __restrict__ gam,
                        const float* __restrict__ bet) {
    int idx = blockIdx.x * blockDim.x + threadIdx.x;
    const int total = N_NODES * H / 4;
    if (idx >= total) return;
    int f = (idx & (H / 4 - 1)) * 4;
    float4 hc  = ((const float4*)g_hc)[idx];
    float4 hv  = ((float4*)g_h)[idx];
    float4 mu4 = *(const float4*)(g_bn + f);
    float4 rs4 = *(const float4*)(g_bn + H + f);
    float4 gg  = *(const float4*)(gam + f);
    float4 bb  = *(const float4*)(bet + f);

    float x0 = (hc.x - mu4.x) * rs4.x * gg.x + bb.x;
    float x1 = (hc.y - mu4.y) * rs4.y * gg.y + bb.y;
    float x2 = (hc.z - mu4.z) * rs4.z * gg.z + bb.z;
    float x3 = (hc.w - mu4.w) * rs4.w * gg.w + bb.w;
    hv.x += x0 * normcdff(x0);
    hv.y += x1 * normcdff(x1);
    hv.z += x2 * normcdff(x2);
    hv.w += x3 * normcdff(x3);
    ((float4*)g_h)[idx] = hv;
}

__global__ void k_pool(const int* __restrict__ batch) {
    int j = threadIdx.x;
    int chunk = (N_NODES + gridDim.x - 1) / gridDim.x;
    int i0 = blockIdx.x * chunk;
    int i1 = min(N_NODES, i0 + chunk);
    if (i0 >= i1) return;
    int curG = batch[i0];
    float acc = 0.f;
    int run = 0;
    for (int i = i0; i < i1; i++) {
        int g = batch[i];
        float v = g_h[(size_t)i * H + j];
        if (g != curG) {
            atomicAdd(&g_hp[curG * H + j], acc);
            if (j == 0) atomicAdd(&g_cntg[curG], (float)run);
            acc = 0.f; run = 0; curG = g;
        }
        acc += v; run++;
    }
    atomicAdd(&g_hp[curG * H + j], acc);
    if (j == 0) atomicAdd(&g_cntg[curG], (float)run);
}

__global__ void k_out(const float* __restrict__ W,
                      const float* __restrict__ b,
                      float* __restrict__ out) {
    int g = blockIdx.x;
    int j = threadIdx.x;
    const float* hp = g_hp + g * H;
    float acc = g_cntg[g] * b[j];
#pragma unroll 8
    for (int k = 0; k < H; k++)
        acc = fmaf(hp[k], W[k * OUT_F + j], acc);
    out[g * OUT_F + j] = acc;
}

extern "C" void kernel_launch(void* const* d_in, const int* in_sizes, int n_in,
                              void* d_out, int out_size) {
    const float* x      = (const float*)d_in[0];
    const int*   ei     = (const int*)  d_in[1];
    const float* attr   = (const float*)d_in[2];
    const int*   batch  = (const int*)  d_in[3];
    const float* emb_W  = (const float*)d_in[4];
    const float* emb_b  = (const float*)d_in[5];
    const float* edge_W = (const float*)d_in[6];
    const float* edge_b = (const float*)d_in[7];
    const float* nn_W   = (const float*)d_in[8];
    const float* nn_b   = (const float*)d_in[9];
    const float* bn_g   = (const float*)d_in[10];
    const float* bn_b   = (const float*)d_in[11];
    const float* lin_W  = (const float*)d_in[12];
    const float* lin_b  = (const float*)d_in[13];
    float* out = (float*)d_out;

    cudaFuncSetAttribute(k_nodegemm,
                         cudaFuncAttributeMaxDynamicSharedMemorySize,
                         H * H * (int)sizeof(float));

    const int ew_grid = (N_NODES * H / 4 + 255) / 256;
    const int eg      = (N_EDGES + 255) / 256;
    const int mega    = MEGA_EMBED_BLKS + MEGA_HIST_BLKS + MEGA_ZERO_BLKS;

    k_megainit<<<mega, 128>>>(x, emb_W, emb_b, ei);          // my launch 0
    k_scanfused<<<SCAN_NBLK, SCAN_CHUNK>>>();                 // 1
    k_fillsort<<<eg, 256>>>(ei, attr);                        // 2
    for (int l = 0; l < NLAYERS; l++) {
        k_gatheragg<<<(N_NODES + 7) / 8, 256>>>(              // 3 -> ncu target (global #5)
            edge_W + (size_t)l * E_FEAT * H, edge_b + (size_t)l * H);
        k_nodegemm<<<296, 256, H * H * sizeof(float)>>>(
            nn_W + (size_t)l * H * H, nn_b + (size_t)l * H);
        k_bnstats<<<1, H>>>();
        k_apply<<<ew_grid, 256>>>(bn_g + (size_t)l * H, bn_b + (size_t)l * H);
    }
    k_pool<<<1024, 128>>>(batch);
    k_out<<<NG, OUT_F>>>(lin_W, lin_b, out);
}

// round 8
// speedup vs baseline: 1.2035x; 1.2035x over previous
#include <cuda_runtime.h>

#define N_NODES 100000
#define N_EDGES 1600000
#define F_INP   8
#define H       128
#define NLAYERS 4
#define E_FEAT  16
#define NG      256
#define OUT_F   256

#define SCAN_CHUNK 512
#define SCAN_NBLK  196   // 196*512 = 100352 >= N_NODES
#define WE 64            // edges per warp window (1.6M / 64 = 25000 windows)

typedef unsigned long long u64;

// ---------------- scratch (device globals; allocations forbidden) ----------------
__device__ __align__(16) float g_h   [(size_t)N_NODES * H];
__device__ __align__(16) float g_agg [(size_t)N_NODES * H];   // seeded with h, gather adds
__device__ __align__(16) float g_hc  [(size_t)N_NODES * H];
__device__ __align__(16) float g_stats[2 * H];
__device__ __align__(16) float g_bn   [2 * H];
__device__ __align__(16) float g_hp  [NG * H];
__device__ float g_cntg[NG];

__device__ __align__(16) int g_cnt_i [N_NODES];   // degree; self-cleaned by k_fill
__device__ int g_rowptr[N_NODES + 1];
__device__ int g_cursor[N_NODES];
__device__ __align__(8) int2 g_sd[N_EDGES];       // (src, dst) in CSR order
// attr in CSR order, each value duplicated as (a,a) for direct f32x2 FMA
__device__ __align__(16) u64 g_attrs2[(size_t)N_EDGES * E_FEAT];

// ---------------- f32x2 helpers ----------------
__device__ __forceinline__ u64 pk2(float x, float y) {
    u64 r; asm("mov.b64 %0,{%1,%2};" : "=l"(r) : "f"(x), "f"(y)); return r;
}
__device__ __forceinline__ void up2(u64 p, float& x, float& y) {
    asm("mov.b64 {%0,%1},%2;" : "=f"(x), "=f"(y) : "l"(p));
}
__device__ __forceinline__ u64 fma2(u64 a, u64 b, u64 c) {
    u64 d; asm("fma.rn.f32x2 %0,%1,%2,%3;" : "=l"(d) : "l"(a), "l"(b), "l"(c)); return d;
}
__device__ __forceinline__ void flushagg(int d, int lane, float4 v) {
    float* p = g_agg + (size_t)d * H + lane * 4;
    asm volatile("red.global.add.v4.f32 [%0], {%1,%2,%3,%4};"
                 :: "l"(p), "f"(v.x), "f"(v.y), "f"(v.z), "f"(v.w) : "memory");
}

// ================= my launch 0: embed (h AND agg seed) + degree hist + zero =================
#define MEGA_EMBED_BLKS  N_NODES
#define MEGA_HIST_BLKS   ((N_EDGES + 127) / 128)
#define MEGA_ZERO_BLKS   ((NG * H + 127) / 128)
__global__ void k_megainit(const float* __restrict__ x,
                           const float* __restrict__ W,
                           const float* __restrict__ b,
                           const int* __restrict__ ei) {
    int blk = blockIdx.x;
    int t = threadIdx.x;
    if (blk < MEGA_EMBED_BLKS) {
        const float* xr = x + (size_t)blk * F_INP;
        float acc = b[t];
#pragma unroll
        for (int k = 0; k < F_INP; k++)
            acc = fmaf(xr[k], W[k * H + t], acc);
        g_h  [(size_t)blk * H + t] = acc;
        g_agg[(size_t)blk * H + t] = acc;    // seed for layer-0 gather flushes
        return;
    }
    blk -= MEGA_EMBED_BLKS;
    if (blk < MEGA_HIST_BLKS) {
        int e = blk * 128 + t;
        if (e < N_EDGES) atomicAdd(&g_cnt_i[ei[N_EDGES + e]], 1);
        return;
    }
    blk -= MEGA_HIST_BLKS;
    int i = blk * 128 + t;
    if (i < NG * H) g_hp[i] = 0.f;
    if (i < NG)     g_cntg[i] = 0.f;
}

// ================= my launch 1: fused exclusive scan -> rowptr, cursor =================
__global__ void __launch_bounds__(SCAN_CHUNK) k_scanfused() {
    __shared__ int s[SCAN_CHUNK];
    __shared__ int sb[SCAN_CHUNK];
    int t = threadIdx.x;
    int lim = blockIdx.x * SCAN_CHUNK;

    int acc = 0;
    const int4* c4 = (const int4*)g_cnt_i;
    for (int i4 = t; i4 < lim / 4; i4 += SCAN_CHUNK) {
        int4 v = c4[i4];
        acc += v.x + v.y + v.z + v.w;
    }
    sb[t] = acc; __syncthreads();
    for (int o = SCAN_CHUNK / 2; o > 0; o >>= 1) {
        if (t < o) sb[t] += sb[t + o];
        __syncthreads();
    }
    int base = sb[0];

    int i = lim + t;
    int v = (i < N_NODES) ? g_cnt_i[i] : 0;
    s[t] = v; __syncthreads();
    for (int o = 1; o < SCAN_CHUNK; o <<= 1) {
        int tv = (t >= o) ? s[t - o] : 0;
        __syncthreads();
        s[t] += tv;
        __syncthreads();
    }
    if (i < N_NODES) {
        int ex = base + s[t] - v;
        g_rowptr[i] = ex;
        g_cursor[i] = ex;
        if (i == N_NODES - 1) g_rowptr[N_NODES] = base + s[t];
    }
}

// ================= my launch 2: fill CSR directly (src/dst + dup-packed attr) =================
__global__ void k_fill(const int* __restrict__ ei, const float* __restrict__ attr) {
    int e = blockIdx.x * blockDim.x + threadIdx.x;
    if (e < N_NODES) g_cnt_i[e] = 0;      // dead after scan; self-clean for replay
    if (e >= N_EDGES) return;
    int d = ei[N_EDGES + e];
    int pos = atomicAdd(&g_cursor[d], 1);
    g_sd[pos] = make_int2(ei[e], d);
    const float4* ar = (const float4*)(attr + (size_t)e * E_FEAT);
    u64* aw = g_attrs2 + (size_t)pos * E_FEAT;
#pragma unroll
    for (int q = 0; q < 4; q++) {
        float4 a = ar[q];
        aw[q * 4 + 0] = pk2(a.x, a.x);
        aw[q * 4 + 1] = pk2(a.y, a.y);
        aw[q * 4 + 2] = pk2(a.z, a.z);
        aw[q * 4 + 3] = pk2(a.w, a.w);
    }
}

// ================= my launch 3 (+3 more per layer): windowed gather+aggregate =================
// Each warp owns WE consecutive CSR edges; accumulates relu(h[src]+attr@W+b) in
// registers; flushes partial sums per dst via red.global.add.v4 into g_agg
// (pre-seeded with h). Perfect load balance, streaming attr, prefetch depth 1.
__global__ void __launch_bounds__(256) k_gatheragg(const float* __restrict__ W,
                                                   const float* __restrict__ b) {
    int lane = threadIdx.x & 31;
    int win = (blockIdx.x * 256 + threadIdx.x) >> 5;
    int e0 = win * WE;
    if (e0 >= N_EDGES) return;
    int e1 = e0 + WE;
    if (e1 > N_EDGES) e1 = N_EDGES;

    u64 w01[E_FEAT], w23[E_FEAT];
#pragma unroll
    for (int k = 0; k < E_FEAT; k++) {
        ulonglong2 wp = *(const ulonglong2*)(W + k * H + lane * 4);
        w01[k] = wp.x; w23[k] = wp.y;
    }
    float4 bb = *(const float4*)(b + lane * 4);
    u64 b01 = pk2(bb.x, bb.y), b23 = pk2(bb.z, bb.w);

    float4 acc = make_float4(0.f, 0.f, 0.f, 0.f);
    int2 sd = g_sd[e0];
    int dcur = sd.y;
    float4 hc = *(const float4*)(g_h + (size_t)sd.x * H + lane * 4);

    for (int e = e0; e < e1; e++) {
        // prefetch next edge's (src,dst) and h row
        bool more = (e + 1 < e1);
        int2 sdn = more ? g_sd[e + 1] : make_int2(0, dcur);
        float4 hn = hc;
        if (more) hn = *(const float4*)(g_h + (size_t)sdn.x * H + lane * 4);

        const ulonglong2* ap = (const ulonglong2*)(g_attrs2 + (size_t)e * E_FEAT);
        u64 p01 = b01, p23 = b23;
#pragma unroll
        for (int k2 = 0; k2 < E_FEAT / 2; k2++) {
            ulonglong2 aa = ap[k2];
            p01 = fma2(aa.x, w01[2 * k2],     p01);
            p23 = fma2(aa.x, w23[2 * k2],     p23);
            p01 = fma2(aa.y, w01[2 * k2 + 1], p01);
            p23 = fma2(aa.y, w23[2 * k2 + 1], p23);
        }
        float m0, m1, m2, m3;
        up2(p01, m0, m1); up2(p23, m2, m3);
        acc.x += fmaxf(hc.x + m0, 0.f);
        acc.y += fmaxf(hc.y + m1, 0.f);
        acc.z += fmaxf(hc.z + m2, 0.f);
        acc.w += fmaxf(hc.w + m3, 0.f);

        if (sdn.y != dcur) {               // next edge starts a new dst -> flush
            flushagg(dcur, lane, acc);
            acc = make_float4(0.f, 0.f, 0.f, 0.f);
        }
        dcur = sdn.y;
        hc = hn;
    }
    flushagg(dcur, lane, acc);
}

// ================= node GEMM: hc = agg @ nn_W + nn_b ; BN sum/sumsq =================
__global__ void __launch_bounds__(256) k_nodegemm(const float* __restrict__ W,
                                                  const float* __restrict__ b) {
    extern __shared__ float sW[];   // 64KB
    for (int idx = threadIdx.x; idx < H * H / 4; idx += blockDim.x)
        ((float4*)sW)[idx] = ((const float4*)W)[idx];
    __syncthreads();

    int lane = threadIdx.x & 31;
    int wid  = (blockIdx.x * blockDim.x + threadIdx.x) >> 5;
    int nw   = (gridDim.x * blockDim.x) >> 5;
    float4 bb = *(const float4*)(b + lane * 4);
    u64 bias01 = pk2(bb.x, bb.y), bias23 = pk2(bb.z, bb.w);

    float4 sum = make_float4(0, 0, 0, 0);
    float4 sq  = make_float4(0, 0, 0, 0);

    for (int i0 = wid * 8; i0 < N_NODES; i0 += nw * 8) {
        u64 acc01[8], acc23[8];
#pragma unroll
        for (int n = 0; n < 8; n++) { acc01[n] = bias01; acc23[n] = bias23; }

#pragma unroll 4
        for (int k4 = 0; k4 < H; k4 += 4) {
            float4 av[8];
#pragma unroll
            for (int n = 0; n < 8; n++)
                av[n] = *(const float4*)(g_agg + (size_t)(i0 + n) * H + k4);
#pragma unroll
            for (int kk = 0; kk < 4; kk++) {
                ulonglong2 wp = *(const ulonglong2*)(sW + (k4 + kk) * H + lane * 4);
#pragma unroll
                for (int n = 0; n < 8; n++) {
                    float a = (kk == 0) ? av[n].x : (kk == 1) ? av[n].y
                             : (kk == 2) ? av[n].z : av[n].w;
                    u64 ap = pk2(a, a);
                    acc01[n] = fma2(ap, wp.x, acc01[n]);
                    acc23[n] = fma2(ap, wp.y, acc23[n]);
                }
            }
        }
#pragma unroll
        for (int n = 0; n < 8; n++) {
            float x0, x1, x2, x3;
            up2(acc01[n], x0, x1); up2(acc23[n], x2, x3);
            *(float4*)(g_hc + (size_t)(i0 + n) * H + lane * 4) =
                make_float4(x0, x1, x2, x3);
            sum.x += x0; sum.y += x1; sum.z += x2; sum.w += x3;
            sq.x += x0 * x0; sq.y += x1 * x1; sq.z += x2 * x2; sq.w += x3 * x3;
        }
    }
    int f = lane * 4;
    atomicAdd(&g_stats[f + 0], sum.x);
    atomicAdd(&g_stats[f + 1], sum.y);
    atomicAdd(&g_stats[f + 2], sum.z);
    atomicAdd(&g_stats[f + 3], sum.w);
    atomicAdd(&g_stats[H + f + 0], sq.x);
    atomicAdd(&g_stats[H + f + 1], sq.y);
    atomicAdd(&g_stats[H + f + 2], sq.z);
    atomicAdd(&g_stats[H + f + 3], sq.w);
}

__global__ void k_bnstats() {
    int j = threadIdx.x;
    float s = g_stats[j];
    float q = g_stats[H + j];
    const float inv = 1.0f / (float)N_NODES;
    float mu  = s * inv;
    float var = q * inv - mu * mu;
    g_bn[j]     = mu;
    g_bn[H + j] = rsqrtf(var + 1e-5f);
    g_stats[j] = 0.f;
    g_stats[H + j] = 0.f;
}

// apply BN + exact GELU + residual; writes h AND re-seeds agg for next layer
__global__ void k_apply(const float* __restrict__ gam,
                        const float* __restrict__ bet) {
    int idx = blockIdx.x * blockDim.x + threadIdx.x;
    const int total = N_NODES * H / 4;
    if (idx >= total) return;
    int f = (idx & (H / 4 - 1)) * 4;
    float4 hc  = ((const float4*)g_hc)[idx];
    float4 hv  = ((float4*)g_h)[idx];
    float4 mu4 = *(const float4*)(g_bn + f);
    float4 rs4 = *(const float4*)(g_bn + H + f);
    float4 gg  = *(const float4*)(gam + f);
    float4 bb  = *(const float4*)(bet + f);

    float x0 = (hc.x - mu4.x) * rs4.x * gg.x + bb.x;
    float x1 = (hc.y - mu4.y) * rs4.y * gg.y + bb.y;
    float x2 = (hc.z - mu4.z) * rs4.z * gg.z + bb.z;
    float x3 = (hc.w - mu4.w) * rs4.w * gg.w + bb.w;
    hv.x += x0 * normcdff(x0);
    hv.y += x1 * normcdff(x1);
    hv.z += x2 * normcdff(x2);
    hv.w += x3 * normcdff(x3);
    ((float4*)g_h)[idx]   = hv;
    ((float4*)g_agg)[idx] = hv;      // seed for next layer's gather flushes
}

__global__ void k_pool(const int* __restrict__ batch) {
    int j = threadIdx.x;
    int chunk = (N_NODES + gridDim.x - 1) / gridDim.x;
    int i0 = blockIdx.x * chunk;
    int i1 = min(N_NODES, i0 + chunk);
    if (i0 >= i1) return;
    int curG = batch[i0];
    float acc = 0.f;
    int run = 0;
    for (int i = i0; i < i1; i++) {
        int g = batch[i];
        float v = g_h[(size_t)i * H + j];
        if (g != curG) {
            atomicAdd(&g_hp[curG * H + j], acc);
            if (j == 0) atomicAdd(&g_cntg[curG], (float)run);
            acc = 0.f; run = 0; curG = g;
        }
        acc += v; run++;
    }
    atomicAdd(&g_hp[curG * H + j], acc);
    if (j == 0) atomicAdd(&g_cntg[curG], (float)run);
}

__global__ void k_out(const float* __restrict__ W,
                      const float* __restrict__ b,
                      float* __restrict__ out) {
    int g = blockIdx.x;
    int j = threadIdx.x;
    const float* hp = g_hp + g * H;
    float acc = g_cntg[g] * b[j];
#pragma unroll 8
    for (int k = 0; k < H; k++)
        acc = fmaf(hp[k], W[k * OUT_F + j], acc);
    out[g * OUT_F + j] = acc;
}

extern "C" void kernel_launch(void* const* d_in, const int* in_sizes, int n_in,
                              void* d_out, int out_size) {
    const float* x      = (const float*)d_in[0];
    const int*   ei     = (const int*)  d_in[1];
    const float* attr   = (const float*)d_in[2];
    const int*   batch  = (const int*)  d_in[3];
    const float* emb_W  = (const float*)d_in[4];
    const float* emb_b  = (const float*)d_in[5];
    const float* edge_W = (const float*)d_in[6];
    const float* edge_b = (const float*)d_in[7];
    const float* nn_W   = (const float*)d_in[8];
    const float* nn_b   = (const float*)d_in[9];
    const float* bn_g   = (const float*)d_in[10];
    const float* bn_b   = (const float*)d_in[11];
    const float* lin_W  = (const float*)d_in[12];
    const float* lin_b  = (const float*)d_in[13];
    float* out = (float*)d_out;

    cudaFuncSetAttribute(k_nodegemm,
                         cudaFuncAttributeMaxDynamicSharedMemorySize,
                         H * H * (int)sizeof(float));

    const int ew_grid = (N_NODES * H / 4 + 255) / 256;
    const int eg      = (N_EDGES + 255) / 256;
    const int mega    = MEGA_EMBED_BLKS + MEGA_HIST_BLKS + MEGA_ZERO_BLKS;
    const int nwin    = (N_EDGES + WE - 1) / WE;          // 25000
    const int ggrid   = (nwin + 7) / 8;                   // 3125 blocks

    k_megainit<<<mega, 128>>>(x, emb_W, emb_b, ei);      // my launch 0
    k_scanfused<<<SCAN_NBLK, SCAN_CHUNK>>>();             // 1
    k_fill<<<eg, 256>>>(ei, attr);                        // 2
    for (int l = 0; l < NLAYERS; l++) {
        k_gatheragg<<<ggrid, 256>>>(                      // 3 -> ncu global #5
            edge_W + (size_t)l * E_FEAT * H, edge_b + (size_t)l * H);
        k_nodegemm<<<296, 256, H * H * sizeof(float)>>>(
            nn_W + (size_t)l * H * H, nn_b + (size_t)l * H);
        k_bnstats<<<1, H>>>();
        k_apply<<<ew_grid, 256>>>(bn_g + (size_t)l * H, bn_b + (size_t)l * H);
    }
    k_pool<<<1024, 128>>>(batch);
    k_out<<<NG, OUT_F>>>(lin_W, lin_b, out);
}